// round 10
// baseline (speedup 1.0000x reference)
#include <cuda_runtime.h>
#include <cuda_fp16.h>
#include <math.h>
#include <stdint.h>

#define NN 8192
#define FD 128
#define HEPS 1e-7f
#define MAXT (1.0f - 1e-6f)
#define PA 132    // A/C smem row pad
#define PB 136    // B smem row pad
#define PA2 260   // gemm2 A row pad
#define CAP 256   // nnz capacity/row (mean 82, sd 9; max ~130)

// Scratch (no allocations allowed)
__device__ __half g_Vh[NN * FD];
__device__ __half g_Wh[NN * 2 * FD];
__device__ int    g_cnt[NN];
__device__ uint2  g_pairs[NN * CAP];   // .x = col, .y = float bits of adj value

__device__ __forceinline__ float wsum(float v) {
#pragma unroll
    for (int o = 16; o > 0; o >>= 1) v += __shfl_xor_sync(0xffffffffu, v, o);
    return v;
}

__device__ __forceinline__ uint32_t f2tf(float f) {
    uint32_t u;
    asm("cvt.rna.tf32.f32 %0, %1;" : "=r"(u) : "f"(f));
    return u;
}

__device__ __forceinline__ void mma_tf32(float c[4], uint32_t a0, uint32_t a1,
                                         uint32_t a2, uint32_t a3,
                                         uint32_t b0, uint32_t b1) {
    asm volatile(
        "mma.sync.aligned.m16n8k8.row.col.f32.tf32.tf32.f32 "
        "{%0,%1,%2,%3},{%4,%5,%6,%7},{%8,%9},{%0,%1,%2,%3};"
        : "+f"(c[0]), "+f"(c[1]), "+f"(c[2]), "+f"(c[3])
        : "r"(a0), "r"(a1), "r"(a2), "r"(a3), "r"(b0), "r"(b1));
}

// Mobius epilogue from smem-staged accumulators; warp owns 4 rows.
// MODE 0: log0(h_add(exp0(T),b)) -> half; MODE 1: h_add(exp0(T),b) -> float
template <int MODE>
__device__ __forceinline__ void mobius_smem(const float* __restrict__ Cs,
                                            const float* __restrict__ bias,
                                            int br, int wid, int lane,
                                            void* __restrict__ out) {
    float4 bv = ((const float4*)bias)[lane];
    float y2 = wsum(bv.x * bv.x + bv.y * bv.y + bv.z * bv.z + bv.w * bv.w);
#pragma unroll
    for (int r = 0; r < 4; r++) {
        int lrow = wid * 4 + r;
        int row = br + lrow;
        float4 t = ((const float4*)(Cs + lrow * PA))[lane];
        float t0 = t.x, t1 = t.y, t2 = t.z, t3 = t.w;
        float ss  = wsum(t0 * t0 + t1 * t1 + t2 * t2 + t3 * t3);
        float dtb = wsum(t0 * bv.x + t1 * bv.y + t2 * bv.z + t3 * bv.w);
        float n = fmaxf(sqrtf(ss), HEPS);
        float s = tanhf(n) / n;
        float x2 = s * s * ss;
        float xy = s * dtb;
        float cnum = 1.f + 2.f * xy + y2;
        float cx = 1.f - x2;
        float inv = 1.f / fmaxf(1.f + 2.f * xy + x2 * y2, HEPS);
        float o0 = (cnum * s * t0 + cx * bv.x) * inv;
        float o1 = (cnum * s * t1 + cx * bv.y) * inv;
        float o2 = (cnum * s * t2 + cx * bv.z) * inv;
        float o3 = (cnum * s * t3 + cx * bv.w) * inv;
        if (MODE == 0) {
            float sso = wsum(o0 * o0 + o1 * o1 + o2 * o2 + o3 * o3);
            float no = fmaxf(sqrtf(sso), HEPS);
            float so = atanhf(fminf(no, MAXT)) / no;
            o0 *= so; o1 *= so; o2 *= so; o3 *= so;
            __half2 h0 = __floats2half2_rn(o0, o1);
            __half2 h1 = __floats2half2_rn(o2, o3);
            ((uint2*)((__half*)out + (size_t)row * FD))[lane] =
                make_uint2(*(uint32_t*)&h0, *(uint32_t*)&h1);
        } else {
            ((float4*)((float*)out + (size_t)row * FD))[lane] =
                make_float4(o0, o1, o2, o3);
        }
    }
}

// ---------------------------------------------------------------------------
// k1 role-split kernel:
//   blocks [0,256):    GEMM1 (tf32 mma, BM=32): V = log0(h_add(exp0(log0(x)@embed),eb))
//   blocks [256,1280): adj compression: warp/row ballot-compact to (col,val) CSR
// The compress CTAs saturate DRAM while gemm1 CTAs do tensor work.
// ---------------------------------------------------------------------------
__global__ __launch_bounds__(256) void k_fused1(
    const float* __restrict__ X, const float* __restrict__ B,
    const float* __restrict__ bias, __half* __restrict__ out,
    const float* __restrict__ adj) {
    const int tid = threadIdx.x;
    const int lane = tid & 31;
    const int wid = tid >> 5;

    if (blockIdx.x >= 256) {
        // ---------------- adj -> CSR compression ----------------
        int row = (blockIdx.x - 256) * 8 + wid;
        const float4* a4 = (const float4*)(adj + (size_t)row * NN);
        const unsigned lt = (1u << lane) - 1u;
        uint2* pr = g_pairs + (size_t)row * CAP;
        int cnt = 0;
#pragma unroll 1
        for (int it = 0; it < 64; it += 4) {
            float4 a[4];
#pragma unroll
            for (int j = 0; j < 4; j++) a[j] = __ldcs(&a4[(it + j) * 32 + lane]);
#pragma unroll
            for (int j = 0; j < 4; j++) {
                float vv[4] = {a[j].x, a[j].y, a[j].z, a[j].w};
#pragma unroll
                for (int c = 0; c < 4; c++) {
                    float v = vv[c];
                    unsigned m = __ballot_sync(0xffffffffu, v != 0.f);
                    if (v != 0.f) {
                        int pos = cnt + __popc(m & lt);
                        if (pos < CAP)
                            pr[pos] = make_uint2(((it + j) * 32 + lane) * 4 + c,
                                                 __float_as_uint(v));
                    }
                    cnt += __popc(m);
                }
            }
        }
        if (lane == 0) g_cnt[row] = cnt < CAP ? cnt : CAP;
        return;
    }

    // ---------------- GEMM1 (proven R6/R8 body) ----------------
    extern __shared__ char smraw[];
    float*    Asf = (float*)smraw;                       // [32][PA]
    uint32_t* Asu = (uint32_t*)smraw;
    uint32_t* Bsu = (uint32_t*)(smraw + 32 * PA * 4);    // [128][PB]
    float*    Cs  = (float*)smraw;                       // [32][PA] (reuse)
    const int br = blockIdx.x * 32;

#pragma unroll
    for (int i = 0; i < 4; i++) {
        int idx4 = tid + i * 256;
        int r = idx4 >> 5, c4 = idx4 & 31;
        ((float4*)(Asf + r * PA))[c4] = ((const float4*)(X + (size_t)(br + r) * FD))[c4];
    }
#pragma unroll
    for (int i = 0; i < 16; i++) {
        int idx4 = tid + i * 256;
        int k = idx4 >> 5, c4 = idx4 & 31;
        float4 v = ((const float4*)B)[idx4];
        ((uint4*)(Bsu + k * PB))[c4] =
            make_uint4(f2tf(v.x), f2tf(v.y), f2tf(v.z), f2tf(v.w));
    }
    __syncthreads();

#pragma unroll
    for (int r = 0; r < 4; r++) {
        int row = wid * 4 + r;
        float4 v = ((float4*)(Asf + row * PA))[lane];
        float ss = wsum(v.x * v.x + v.y * v.y + v.z * v.z + v.w * v.w);
        float n = fmaxf(sqrtf(ss), HEPS);
        float s = atanhf(fminf(n, MAXT)) / n;
        ((uint4*)(Asu + row * PA))[lane] =
            make_uint4(f2tf(v.x * s), f2tf(v.y * s), f2tf(v.z * s), f2tf(v.w * s));
    }
    __syncthreads();

    const int qr = lane >> 2, qc = lane & 3;
    const int wm = (wid >> 2) * 16;
    const int wn = (wid & 3) * 32;
    float acc[4][4];
#pragma unroll
    for (int nt = 0; nt < 4; nt++)
#pragma unroll
        for (int c = 0; c < 4; c++) acc[nt][c] = 0.f;

#pragma unroll
    for (int ks = 0; ks < 16; ks++) {
        int k0 = ks * 8;
        uint32_t a0 = Asu[(wm + qr) * PA + k0 + qc];
        uint32_t a1 = Asu[(wm + 8 + qr) * PA + k0 + qc];
        uint32_t a2 = Asu[(wm + qr) * PA + k0 + 4 + qc];
        uint32_t a3 = Asu[(wm + 8 + qr) * PA + k0 + 4 + qc];
#pragma unroll
        for (int nt = 0; nt < 4; nt++) {
            int nb = wn + nt * 8;
            uint32_t b0 = Bsu[(k0 + qc) * PB + nb + qr];
            uint32_t b1 = Bsu[(k0 + 4 + qc) * PB + nb + qr];
            mma_tf32(acc[nt], a0, a1, a2, a3, b0, b1);
        }
    }
    __syncthreads();

#pragma unroll
    for (int nt = 0; nt < 4; nt++) {
        int col = wn + nt * 8 + 2 * qc;
        *(float2*)&Cs[(wm + qr) * PA + col]     = make_float2(acc[nt][0], acc[nt][1]);
        *(float2*)&Cs[(wm + 8 + qr) * PA + col] = make_float2(acc[nt][2], acc[nt][3]);
    }
    __syncthreads();

    mobius_smem<0>(Cs, bias, br, wid, lane, out);
}

// ---------------------------------------------------------------------------
// k2: CSR gather + fused epilogue: W = log0(concat(x, exp0(adj @ V)))
// One warp per row; 8-wide unrolled gathers of fp16 V rows (MLP 8).
// ---------------------------------------------------------------------------
__global__ __launch_bounds__(256) void k_gather(
    const __half* __restrict__ V, const float* __restrict__ x,
    __half* __restrict__ W) {
    int row = (blockIdx.x * blockDim.x + threadIdx.x) >> 5;
    int lane = threadIdx.x & 31;
    if (row >= NN) return;
    const int cnt = g_cnt[row];
    const uint2* pr = g_pairs + (size_t)row * CAP;
    float ax = 0.f, ay = 0.f, az = 0.f, aw = 0.f;

    int i = 0;
    for (; i + 8 <= cnt; i += 8) {
        uint4 q[4];
#pragma unroll
        for (int j = 0; j < 4; j++) q[j] = *(const uint4*)(pr + i + 2 * j);
        int   col[8];
        float val[8];
#pragma unroll
        for (int j = 0; j < 4; j++) {
            col[2 * j]     = (int)q[j].x; val[2 * j]     = __uint_as_float(q[j].y);
            col[2 * j + 1] = (int)q[j].z; val[2 * j + 1] = __uint_as_float(q[j].w);
        }
#pragma unroll
        for (int j = 0; j < 8; j++) {
            uint2 raw = ((const uint2*)(V + (size_t)col[j] * FD))[lane];
            float2 v01 = __half22float2(*(const __half2*)&raw.x);
            float2 v23 = __half22float2(*(const __half2*)&raw.y);
            ax += val[j] * v01.x; ay += val[j] * v01.y;
            az += val[j] * v23.x; aw += val[j] * v23.y;
        }
    }
    for (; i < cnt; i++) {
        uint2 p = pr[i];
        float aj = __uint_as_float(p.y);
        uint2 raw = ((const uint2*)(V + (size_t)p.x * FD))[lane];
        float2 v01 = __half22float2(*(const __half2*)&raw.x);
        float2 v23 = __half22float2(*(const __half2*)&raw.y);
        ax += aj * v01.x; ay += aj * v01.y;
        az += aj * v23.x; aw += aj * v23.y;
    }

    // fused epilogue: W = log0(concat(x, exp0(AV))), written as half
    float ssa = wsum(ax * ax + ay * ay + az * az + aw * aw);
    float na = fmaxf(sqrtf(ssa), HEPS);
    float sa = tanhf(na) / na;
    float4 xv = ((const float4*)(x + (size_t)row * FD))[lane];
    float ssx = wsum(xv.x * xv.x + xv.y * xv.y + xv.z * xv.z + xv.w * xv.w);
    float tot = ssx + sa * sa * ssa;
    float n = fmaxf(sqrtf(tot), HEPS);
    float s = atanhf(fminf(n, MAXT)) / n;
    __half* wr = W + (size_t)row * 2 * FD;
    {
        __half2 h0 = __floats2half2_rn(s * xv.x, s * xv.y);
        __half2 h1 = __floats2half2_rn(s * xv.z, s * xv.w);
        ((uint2*)wr)[lane] = make_uint2(*(uint32_t*)&h0, *(uint32_t*)&h1);
    }
    {
        float sb = s * sa;
        __half2 h0 = __floats2half2_rn(sb * ax, sb * ay);
        __half2 h1 = __floats2half2_rn(sb * az, sb * aw);
        ((uint2*)(wr + FD))[lane] = make_uint2(*(uint32_t*)&h0, *(uint32_t*)&h1);
    }
}

// ---------------------------------------------------------------------------
// GEMM2 (tf32 mma, BM=32): out = h_add(exp0(W @ layer), lb). W is half.
// ---------------------------------------------------------------------------
__global__ __launch_bounds__(256) void k_gemm2(
    const __half* __restrict__ A, const float* __restrict__ B,
    const float* __restrict__ bias, float* __restrict__ out) {
    extern __shared__ char smraw[];
    uint32_t* Asu = (uint32_t*)smraw;                     // [32][PA2]
    uint32_t* Bsu = (uint32_t*)(smraw + 32 * PA2 * 4);    // [128][PB]
    float*    Cs  = (float*)smraw;                        // [32][PA] (reuse)
    const int tid = threadIdx.x;
    const int lane = tid & 31;
    const int wid = tid >> 5;
    const int br = blockIdx.x * 32;

#pragma unroll
    for (int i = 0; i < 4; i++) {
        int idx8 = tid + i * 256;
        int r = idx8 >> 5, c8 = idx8 & 31;
        uint4 raw = ((const uint4*)(A + (size_t)(br + r) * (2 * FD)))[c8];
        const __half2* hp = (const __half2*)&raw;
        uint32_t* dst = Asu + r * PA2 + c8 * 8;
#pragma unroll
        for (int j = 0; j < 4; j++) {
            float2 f = __half22float2(hp[j]);
            dst[2 * j]     = f2tf(f.x);
            dst[2 * j + 1] = f2tf(f.y);
        }
    }

    const int qr = lane >> 2, qc = lane & 3;
    const int wm = (wid >> 2) * 16;
    const int wn = (wid & 3) * 32;
    float acc[4][4];
#pragma unroll
    for (int nt = 0; nt < 4; nt++)
#pragma unroll
        for (int c = 0; c < 4; c++) acc[nt][c] = 0.f;

#pragma unroll
    for (int chunk = 0; chunk < 2; chunk++) {
        __syncthreads();
#pragma unroll
        for (int i = 0; i < 16; i++) {
            int idx4 = tid + i * 256;
            int k = idx4 >> 5, c4 = idx4 & 31;
            float4 v = ((const float4*)(B + (size_t)chunk * FD * FD))[idx4];
            ((uint4*)(Bsu + k * PB))[c4] =
                make_uint4(f2tf(v.x), f2tf(v.y), f2tf(v.z), f2tf(v.w));
        }
        __syncthreads();
#pragma unroll
        for (int ks = 0; ks < 16; ks++) {
            int k0 = ks * 8;
            int ka = chunk * FD + k0;
            uint32_t a0 = Asu[(wm + qr) * PA2 + ka + qc];
            uint32_t a1 = Asu[(wm + 8 + qr) * PA2 + ka + qc];
            uint32_t a2 = Asu[(wm + qr) * PA2 + ka + 4 + qc];
            uint32_t a3 = Asu[(wm + 8 + qr) * PA2 + ka + 4 + qc];
#pragma unroll
            for (int nt = 0; nt < 4; nt++) {
                int nb = wn + nt * 8;
                uint32_t b0 = Bsu[(k0 + qc) * PB + nb + qr];
                uint32_t b1 = Bsu[(k0 + 4 + qc) * PB + nb + qr];
                mma_tf32(acc[nt], a0, a1, a2, a3, b0, b1);
            }
        }
    }
    __syncthreads();

#pragma unroll
    for (int nt = 0; nt < 4; nt++) {
        int col = wn + nt * 8 + 2 * qc;
        *(float2*)&Cs[(wm + qr) * PA + col]     = make_float2(acc[nt][0], acc[nt][1]);
        *(float2*)&Cs[(wm + 8 + qr) * PA + col] = make_float2(acc[nt][2], acc[nt][3]);
    }
    __syncthreads();

    mobius_smem<1>(Cs, bias, br, wid, lane, out);
}

// ---------------------------------------------------------------------------
extern "C" void kernel_launch(void* const* d_in, const int* in_sizes, int n_in,
                              void* d_out, int out_size) {
    const float* x     = (const float*)d_in[0];
    const float* adj   = (const float*)d_in[1];
    const float* embed = (const float*)d_in[2];
    const float* layer = (const float*)d_in[3];
    const float* eb    = (const float*)d_in[4];
    const float* lb    = (const float*)d_in[5];
    float* out = (float*)d_out;
    (void)in_sizes; (void)n_in; (void)out_size;

    __half *pV, *pW;
    cudaGetSymbolAddress((void**)&pV, g_Vh);
    cudaGetSymbolAddress((void**)&pW, g_Wh);

    const int smem1 = (32 * PA + 128 * PB) * 4;   // ~86.5 KB
    const int smem2 = (32 * PA2 + 128 * PB) * 4;  // ~102.9 KB
    cudaFuncSetAttribute(k_fused1, cudaFuncAttributeMaxDynamicSharedMemorySize, smem1);
    cudaFuncSetAttribute(k_gemm2,  cudaFuncAttributeMaxDynamicSharedMemorySize, smem2);

    // 1. [gemm1: V = log0(h_add(exp0(log0(x)@embed),eb))] ∥ [adj -> CSR]
    k_fused1<<<256 + NN / 8, 256, smem1>>>(x, embed, eb, pV, adj);
    // 2. W = log0(concat(x, exp0(adj @ V)))  via CSR gather
    k_gather<<<NN / 8, 256>>>(pV, x, pW);
    // 3. out = h_add(exp0(W @ layer), lb)
    k_gemm2<<<NN / 32, 256, smem2>>>(pW, layer, lb, out);
}

// round 11
// speedup vs baseline: 1.2741x; 1.2741x over previous
#include <cuda_runtime.h>
#include <cuda_fp16.h>
#include <math.h>
#include <stdint.h>

#define NN 8192
#define FD 128
#define HEPS 1e-7f
#define MAXT (1.0f - 1e-6f)
#define PA 132    // A/C smem row pad
#define PB 136    // B smem row pad
#define PA2 260   // gemm2 A row pad
#define CAP 256   // nnz capacity/row (mean 82, sd 9)

// Scratch (no allocations allowed)
__device__ __half g_Vh[NN * FD];
__device__ __half g_Wh[NN * 2 * FD];
__device__ int    g_cnt[NN];
__device__ uint2  g_pairs[NN * CAP];   // .x = col, .y = float bits of adj value

__device__ __forceinline__ float wsum(float v) {
#pragma unroll
    for (int o = 16; o > 0; o >>= 1) v += __shfl_xor_sync(0xffffffffu, v, o);
    return v;
}

__device__ __forceinline__ uint32_t f2tf(float f) {
    uint32_t u;
    asm("cvt.rna.tf32.f32 %0, %1;" : "=r"(u) : "f"(f));
    return u;
}

__device__ __forceinline__ void mma_tf32(float c[4], uint32_t a0, uint32_t a1,
                                         uint32_t a2, uint32_t a3,
                                         uint32_t b0, uint32_t b1) {
    asm volatile(
        "mma.sync.aligned.m16n8k8.row.col.f32.tf32.tf32.f32 "
        "{%0,%1,%2,%3},{%4,%5,%6,%7},{%8,%9},{%0,%1,%2,%3};"
        : "+f"(c[0]), "+f"(c[1]), "+f"(c[2]), "+f"(c[3])
        : "r"(a0), "r"(a1), "r"(a2), "r"(a3), "r"(b0), "r"(b1));
}

// Mobius epilogue from smem-staged accumulators; warp owns 4 rows.
// MODE 0: log0(h_add(exp0(T),b)) -> half; MODE 1: h_add(exp0(T),b) -> float
template <int MODE>
__device__ __forceinline__ void mobius_smem(const float* __restrict__ Cs,
                                            const float* __restrict__ bias,
                                            int br, int wid, int lane,
                                            void* __restrict__ out) {
    float4 bv = ((const float4*)bias)[lane];
    float y2 = wsum(bv.x * bv.x + bv.y * bv.y + bv.z * bv.z + bv.w * bv.w);
#pragma unroll
    for (int r = 0; r < 4; r++) {
        int lrow = wid * 4 + r;
        int row = br + lrow;
        float4 t = ((const float4*)(Cs + lrow * PA))[lane];
        float t0 = t.x, t1 = t.y, t2 = t.z, t3 = t.w;
        float ss  = wsum(t0 * t0 + t1 * t1 + t2 * t2 + t3 * t3);
        float dtb = wsum(t0 * bv.x + t1 * bv.y + t2 * bv.z + t3 * bv.w);
        float n = fmaxf(sqrtf(ss), HEPS);
        float s = tanhf(n) / n;
        float x2 = s * s * ss;
        float xy = s * dtb;
        float cnum = 1.f + 2.f * xy + y2;
        float cx = 1.f - x2;
        float inv = 1.f / fmaxf(1.f + 2.f * xy + x2 * y2, HEPS);
        float o0 = (cnum * s * t0 + cx * bv.x) * inv;
        float o1 = (cnum * s * t1 + cx * bv.y) * inv;
        float o2 = (cnum * s * t2 + cx * bv.z) * inv;
        float o3 = (cnum * s * t3 + cx * bv.w) * inv;
        if (MODE == 0) {
            float sso = wsum(o0 * o0 + o1 * o1 + o2 * o2 + o3 * o3);
            float no = fmaxf(sqrtf(sso), HEPS);
            float so = atanhf(fminf(no, MAXT)) / no;
            o0 *= so; o1 *= so; o2 *= so; o3 *= so;
            __half2 h0 = __floats2half2_rn(o0, o1);
            __half2 h1 = __floats2half2_rn(o2, o3);
            ((uint2*)((__half*)out + (size_t)row * FD))[lane] =
                make_uint2(*(uint32_t*)&h0, *(uint32_t*)&h1);
        } else {
            ((float4*)((float*)out + (size_t)row * FD))[lane] =
                make_float4(o0, o1, o2, o3);
        }
    }
}

// ---------------------------------------------------------------------------
// k1 role-split kernel, LOW-SMEM (34.3 KB -> 4 CTAs/SM):
//   blocks [0,256):    GEMM1 (tf32 mma, BM=32, B in 32-row K-chunks)
//   blocks [256,1280): adj -> CSR compression (warp/row, MLP-16 streams)
// ---------------------------------------------------------------------------
__global__ __launch_bounds__(256) void k_fused1(
    const float* __restrict__ X, const float* __restrict__ B,
    const float* __restrict__ bias, __half* __restrict__ out,
    const float* __restrict__ adj) {
    const int tid = threadIdx.x;
    const int lane = tid & 31;
    const int wid = tid >> 5;

    if (blockIdx.x >= 256) {
        // ---------------- adj -> CSR compression ----------------
        int row = (blockIdx.x - 256) * 8 + wid;
        const float4* a4 = (const float4*)(adj + (size_t)row * NN);
        const unsigned lt = (1u << lane) - 1u;
        uint2* pr = g_pairs + (size_t)row * CAP;
        int cnt = 0;
#pragma unroll 1
        for (int it = 0; it < 64; it += 4) {
            float4 a[4];
#pragma unroll
            for (int j = 0; j < 4; j++) a[j] = __ldcs(&a4[(it + j) * 32 + lane]);
#pragma unroll
            for (int j = 0; j < 4; j++) {
                float vv[4] = {a[j].x, a[j].y, a[j].z, a[j].w};
#pragma unroll
                for (int c = 0; c < 4; c++) {
                    float v = vv[c];
                    unsigned m = __ballot_sync(0xffffffffu, v != 0.f);
                    if (v != 0.f) {
                        int pos = cnt + __popc(m & lt);
                        if (pos < CAP)
                            pr[pos] = make_uint2(((it + j) * 32 + lane) * 4 + c,
                                                 __float_as_uint(v));
                    }
                    cnt += __popc(m);
                }
            }
        }
        if (lane == 0) g_cnt[row] = cnt < CAP ? cnt : CAP;
        return;
    }

    // ---------------- GEMM1 (tf32 mma, K-chunked B) ----------------
    extern __shared__ char smraw[];
    float*    Asf = (float*)smraw;                       // [32][PA]
    uint32_t* Asu = (uint32_t*)smraw;
    uint32_t* Bsu = (uint32_t*)(smraw + 32 * PA * 4);    // [32][PB]
    float*    Cs  = (float*)smraw;                       // [32][PA] (reuse)
    const int br = blockIdx.x * 32;

    // load A fp32
#pragma unroll
    for (int i = 0; i < 4; i++) {
        int idx4 = tid + i * 256;
        int r = idx4 >> 5, c4 = idx4 & 31;
        ((float4*)(Asf + r * PA))[c4] = ((const float4*)(X + (size_t)(br + r) * FD))[c4];
    }
    __syncthreads();

    // log0 scaling + cvt->tf32 in place (warp wid owns rows wid*4..+3)
#pragma unroll
    for (int r = 0; r < 4; r++) {
        int row = wid * 4 + r;
        float4 v = ((float4*)(Asf + row * PA))[lane];
        float ss = wsum(v.x * v.x + v.y * v.y + v.z * v.z + v.w * v.w);
        float n = fmaxf(sqrtf(ss), HEPS);
        float s = atanhf(fminf(n, MAXT)) / n;
        ((uint4*)(Asu + row * PA))[lane] =
            make_uint4(f2tf(v.x * s), f2tf(v.y * s), f2tf(v.z * s), f2tf(v.w * s));
    }

    const int qr = lane >> 2, qc = lane & 3;
    const int wm = (wid >> 2) * 16;
    const int wn = (wid & 3) * 32;
    float acc[4][4];
#pragma unroll
    for (int nt = 0; nt < 4; nt++)
#pragma unroll
        for (int c = 0; c < 4; c++) acc[nt][c] = 0.f;

#pragma unroll
    for (int chunk = 0; chunk < 4; chunk++) {
        // load B rows [chunk*32, +32): 1024 float4 / 256 thr = 4 iters
#pragma unroll
        for (int i = 0; i < 4; i++) {
            int idx4 = tid + i * 256;
            int k = idx4 >> 5, c4 = idx4 & 31;
            float4 v = ((const float4*)(B + (size_t)(chunk * 32 + k) * FD))[c4];
            ((uint4*)(Bsu + k * PB))[c4] =
                make_uint4(f2tf(v.x), f2tf(v.y), f2tf(v.z), f2tf(v.w));
        }
        __syncthreads();   // also orders log0 writes (chunk 0) vs mma reads
#pragma unroll
        for (int ks = 0; ks < 4; ks++) {
            int k0 = ks * 8;
            int ka = chunk * 32 + k0;
            uint32_t a0 = Asu[(wm + qr) * PA + ka + qc];
            uint32_t a1 = Asu[(wm + 8 + qr) * PA + ka + qc];
            uint32_t a2 = Asu[(wm + qr) * PA + ka + 4 + qc];
            uint32_t a3 = Asu[(wm + 8 + qr) * PA + ka + 4 + qc];
#pragma unroll
            for (int nt = 0; nt < 4; nt++) {
                int nb = wn + nt * 8;
                uint32_t b0 = Bsu[(k0 + qc) * PB + nb + qr];
                uint32_t b1 = Bsu[(k0 + 4 + qc) * PB + nb + qr];
                mma_tf32(acc[nt], a0, a1, a2, a3, b0, b1);
            }
        }
        __syncthreads();
    }

    // stage C to smem (reuses A region) -> Mobius epilogue
#pragma unroll
    for (int nt = 0; nt < 4; nt++) {
        int col = wn + nt * 8 + 2 * qc;
        *(float2*)&Cs[(wm + qr) * PA + col]     = make_float2(acc[nt][0], acc[nt][1]);
        *(float2*)&Cs[(wm + 8 + qr) * PA + col] = make_float2(acc[nt][2], acc[nt][3]);
    }
    __syncthreads();

    mobius_smem<0>(Cs, bias, br, wid, lane, out);
}

// ---------------------------------------------------------------------------
// k2: CSR gather + fused epilogue: W = log0(concat(x, exp0(adj @ V)))
// One warp per row; 8-wide unrolled gathers of fp16 V rows.
// ---------------------------------------------------------------------------
__global__ __launch_bounds__(256) void k_gather(
    const __half* __restrict__ V, const float* __restrict__ x,
    __half* __restrict__ W) {
    int row = (blockIdx.x * blockDim.x + threadIdx.x) >> 5;
    int lane = threadIdx.x & 31;
    if (row >= NN) return;
    const int cnt = g_cnt[row];
    const uint2* pr = g_pairs + (size_t)row * CAP;
    float ax = 0.f, ay = 0.f, az = 0.f, aw = 0.f;

    int i = 0;
    for (; i + 8 <= cnt; i += 8) {
        uint4 q[4];
#pragma unroll
        for (int j = 0; j < 4; j++) q[j] = *(const uint4*)(pr + i + 2 * j);
        int   col[8];
        float val[8];
#pragma unroll
        for (int j = 0; j < 4; j++) {
            col[2 * j]     = (int)q[j].x; val[2 * j]     = __uint_as_float(q[j].y);
            col[2 * j + 1] = (int)q[j].z; val[2 * j + 1] = __uint_as_float(q[j].w);
        }
#pragma unroll
        for (int j = 0; j < 8; j++) {
            uint2 raw = ((const uint2*)(V + (size_t)col[j] * FD))[lane];
            float2 v01 = __half22float2(*(const __half2*)&raw.x);
            float2 v23 = __half22float2(*(const __half2*)&raw.y);
            ax += val[j] * v01.x; ay += val[j] * v01.y;
            az += val[j] * v23.x; aw += val[j] * v23.y;
        }
    }
    for (; i < cnt; i++) {
        uint2 p = pr[i];
        float aj = __uint_as_float(p.y);
        uint2 raw = ((const uint2*)(V + (size_t)p.x * FD))[lane];
        float2 v01 = __half22float2(*(const __half2*)&raw.x);
        float2 v23 = __half22float2(*(const __half2*)&raw.y);
        ax += aj * v01.x; ay += aj * v01.y;
        az += aj * v23.x; aw += aj * v23.y;
    }

    float ssa = wsum(ax * ax + ay * ay + az * az + aw * aw);
    float na = fmaxf(sqrtf(ssa), HEPS);
    float sa = tanhf(na) / na;
    float4 xv = ((const float4*)(x + (size_t)row * FD))[lane];
    float ssx = wsum(xv.x * xv.x + xv.y * xv.y + xv.z * xv.z + xv.w * xv.w);
    float tot = ssx + sa * sa * ssa;
    float n = fmaxf(sqrtf(tot), HEPS);
    float s = atanhf(fminf(n, MAXT)) / n;
    __half* wr = W + (size_t)row * 2 * FD;
    {
        __half2 h0 = __floats2half2_rn(s * xv.x, s * xv.y);
        __half2 h1 = __floats2half2_rn(s * xv.z, s * xv.w);
        ((uint2*)wr)[lane] = make_uint2(*(uint32_t*)&h0, *(uint32_t*)&h1);
    }
    {
        float sb = s * sa;
        __half2 h0 = __floats2half2_rn(sb * ax, sb * ay);
        __half2 h1 = __floats2half2_rn(sb * az, sb * aw);
        ((uint2*)(wr + FD))[lane] = make_uint2(*(uint32_t*)&h0, *(uint32_t*)&h1);
    }
}

// ---------------------------------------------------------------------------
// GEMM2 (tf32 mma, BM=32): out = h_add(exp0(W @ layer), lb). W is half.
// ---------------------------------------------------------------------------
__global__ __launch_bounds__(256) void k_gemm2(
    const __half* __restrict__ A, const float* __restrict__ B,
    const float* __restrict__ bias, float* __restrict__ out) {
    extern __shared__ char smraw[];
    uint32_t* Asu = (uint32_t*)smraw;                     // [32][PA2]
    uint32_t* Bsu = (uint32_t*)(smraw + 32 * PA2 * 4);    // [128][PB]
    float*    Cs  = (float*)smraw;                        // [32][PA] (reuse)
    const int tid = threadIdx.x;
    const int lane = tid & 31;
    const int wid = tid >> 5;
    const int br = blockIdx.x * 32;

#pragma unroll
    for (int i = 0; i < 4; i++) {
        int idx8 = tid + i * 256;
        int r = idx8 >> 5, c8 = idx8 & 31;
        uint4 raw = ((const uint4*)(A + (size_t)(br + r) * (2 * FD)))[c8];
        const __half2* hp = (const __half2*)&raw;
        uint32_t* dst = Asu + r * PA2 + c8 * 8;
#pragma unroll
        for (int j = 0; j < 4; j++) {
            float2 f = __half22float2(hp[j]);
            dst[2 * j]     = f2tf(f.x);
            dst[2 * j + 1] = f2tf(f.y);
        }
    }

    const int qr = lane >> 2, qc = lane & 3;
    const int wm = (wid >> 2) * 16;
    const int wn = (wid & 3) * 32;
    float acc[4][4];
#pragma unroll
    for (int nt = 0; nt < 4; nt++)
#pragma unroll
        for (int c = 0; c < 4; c++) acc[nt][c] = 0.f;

#pragma unroll
    for (int chunk = 0; chunk < 2; chunk++) {
        __syncthreads();
#pragma unroll
        for (int i = 0; i < 16; i++) {
            int idx4 = tid + i * 256;
            int k = idx4 >> 5, c4 = idx4 & 31;
            float4 v = ((const float4*)(B + (size_t)chunk * FD * FD))[idx4];
            ((uint4*)(Bsu + k * PB))[c4] =
                make_uint4(f2tf(v.x), f2tf(v.y), f2tf(v.z), f2tf(v.w));
        }
        __syncthreads();
#pragma unroll
        for (int ks = 0; ks < 16; ks++) {
            int k0 = ks * 8;
            int ka = chunk * FD + k0;
            uint32_t a0 = Asu[(wm + qr) * PA2 + ka + qc];
            uint32_t a1 = Asu[(wm + 8 + qr) * PA2 + ka + qc];
            uint32_t a2 = Asu[(wm + qr) * PA2 + ka + 4 + qc];
            uint32_t a3 = Asu[(wm + 8 + qr) * PA2 + ka + 4 + qc];
#pragma unroll
            for (int nt = 0; nt < 4; nt++) {
                int nb = wn + nt * 8;
                uint32_t b0 = Bsu[(k0 + qc) * PB + nb + qr];
                uint32_t b1 = Bsu[(k0 + 4 + qc) * PB + nb + qr];
                mma_tf32(acc[nt], a0, a1, a2, a3, b0, b1);
            }
        }
    }
    __syncthreads();

#pragma unroll
    for (int nt = 0; nt < 4; nt++) {
        int col = wn + nt * 8 + 2 * qc;
        *(float2*)&Cs[(wm + qr) * PA + col]     = make_float2(acc[nt][0], acc[nt][1]);
        *(float2*)&Cs[(wm + 8 + qr) * PA + col] = make_float2(acc[nt][2], acc[nt][3]);
    }
    __syncthreads();

    mobius_smem<1>(Cs, bias, br, wid, lane, out);
}

// ---------------------------------------------------------------------------
extern "C" void kernel_launch(void* const* d_in, const int* in_sizes, int n_in,
                              void* d_out, int out_size) {
    const float* x     = (const float*)d_in[0];
    const float* adj   = (const float*)d_in[1];
    const float* embed = (const float*)d_in[2];
    const float* layer = (const float*)d_in[3];
    const float* eb    = (const float*)d_in[4];
    const float* lb    = (const float*)d_in[5];
    float* out = (float*)d_out;
    (void)in_sizes; (void)n_in; (void)out_size;

    __half *pV, *pW;
    cudaGetSymbolAddress((void**)&pV, g_Vh);
    cudaGetSymbolAddress((void**)&pW, g_Wh);

    const int smem1 = (32 * PA + 32 * PB) * 4;    // ~34.3 KB -> 4 CTAs/SM
    const int smem2 = (32 * PA2 + 128 * PB) * 4;  // ~102.9 KB
    cudaFuncSetAttribute(k_fused1, cudaFuncAttributeMaxDynamicSharedMemorySize, smem1);
    cudaFuncSetAttribute(k_gemm2,  cudaFuncAttributeMaxDynamicSharedMemorySize, smem2);

    // 1. [gemm1: V = log0(h_add(exp0(log0(x)@embed),eb))] ∥ [adj -> CSR]
    k_fused1<<<256 + NN / 8, 256, smem1>>>(x, embed, eb, pV, adj);
    // 2. W = log0(concat(x, exp0(adj @ V)))  via CSR gather
    k_gather<<<NN / 8, 256>>>(pV, x, pW);
    // 3. out = h_add(exp0(W @ layer), lb)
    k_gemm2<<<NN / 32, 256, smem2>>>(pW, layer, lb, out);
}

// round 16
// speedup vs baseline: 1.2895x; 1.0121x over previous
#include <cuda_runtime.h>
#include <cuda_fp16.h>
#include <math.h>
#include <stdint.h>

#define NN 8192
#define FD 128
#define HEPS 1e-7f
#define MAXT (1.0f - 1e-6f)
#define PA 132    // A/C smem row pad
#define PB 136    // B smem row pad
#define PA2 260   // gemm2 A row pad
#define CAP 256   // nnz capacity/row (mean 82, sd 9)

// Scratch (no allocations allowed)
__device__ __half g_Vh[NN * FD];
__device__ __half g_Wh[NN * 2 * FD];
__device__ int    g_cnt[NN];
__device__ uint2  g_pairs[NN * CAP];   // .x = col, .y = float bits of adj value

__device__ __forceinline__ float wsum(float v) {
#pragma unroll
    for (int o = 16; o > 0; o >>= 1) v += __shfl_xor_sync(0xffffffffu, v, o);
    return v;
}

__device__ __forceinline__ uint32_t f2tf(float f) {
    uint32_t u;
    asm("cvt.rna.tf32.f32 %0, %1;" : "=r"(u) : "f"(f));
    return u;
}

__device__ __forceinline__ void mma_tf32(float c[4], uint32_t a0, uint32_t a1,
                                         uint32_t a2, uint32_t a3,
                                         uint32_t b0, uint32_t b1) {
    asm volatile(
        "mma.sync.aligned.m16n8k8.row.col.f32.tf32.tf32.f32 "
        "{%0,%1,%2,%3},{%4,%5,%6,%7},{%8,%9},{%0,%1,%2,%3};"
        : "+f"(c[0]), "+f"(c[1]), "+f"(c[2]), "+f"(c[3])
        : "r"(a0), "r"(a1), "r"(a2), "r"(a3), "r"(b0), "r"(b1));
}

// Mobius epilogue from smem-staged accumulators; warp owns 4 rows.
// MODE 0: log0(h_add(exp0(T),b)) -> half; MODE 1: h_add(exp0(T),b) -> float
template <int MODE>
__device__ __forceinline__ void mobius_smem(const float* __restrict__ Cs,
                                            const float* __restrict__ bias,
                                            int br, int wid, int lane,
                                            void* __restrict__ out) {
    float4 bv = ((const float4*)bias)[lane];
    float y2 = wsum(bv.x * bv.x + bv.y * bv.y + bv.z * bv.z + bv.w * bv.w);
#pragma unroll
    for (int r = 0; r < 4; r++) {
        int lrow = wid * 4 + r;
        int row = br + lrow;
        float4 t = ((const float4*)(Cs + lrow * PA))[lane];
        float t0 = t.x, t1 = t.y, t2 = t.z, t3 = t.w;
        float ss  = wsum(t0 * t0 + t1 * t1 + t2 * t2 + t3 * t3);
        float dtb = wsum(t0 * bv.x + t1 * bv.y + t2 * bv.z + t3 * bv.w);
        float n = fmaxf(sqrtf(ss), HEPS);
        float s = tanhf(n) / n;
        float x2 = s * s * ss;
        float xy = s * dtb;
        float cnum = 1.f + 2.f * xy + y2;
        float cx = 1.f - x2;
        float inv = 1.f / fmaxf(1.f + 2.f * xy + x2 * y2, HEPS);
        float o0 = (cnum * s * t0 + cx * bv.x) * inv;
        float o1 = (cnum * s * t1 + cx * bv.y) * inv;
        float o2 = (cnum * s * t2 + cx * bv.z) * inv;
        float o3 = (cnum * s * t3 + cx * bv.w) * inv;
        if (MODE == 0) {
            float sso = wsum(o0 * o0 + o1 * o1 + o2 * o2 + o3 * o3);
            float no = fmaxf(sqrtf(sso), HEPS);
            float so = atanhf(fminf(no, MAXT)) / no;
            o0 *= so; o1 *= so; o2 *= so; o3 *= so;
            __half2 h0 = __floats2half2_rn(o0, o1);
            __half2 h1 = __floats2half2_rn(o2, o3);
            ((uint2*)((__half*)out + (size_t)row * FD))[lane] =
                make_uint2(*(uint32_t*)&h0, *(uint32_t*)&h1);
        } else {
            ((float4*)((float*)out + (size_t)row * FD))[lane] =
                make_float4(o0, o1, o2, o3);
        }
    }
}

// ---------------------------------------------------------------------------
// k1 role-split kernel, LOW-SMEM (34.3 KB):
//   blocks [0,256):    GEMM1 (tf32 mma, BM=32, B in 32-row K-chunks)
//   blocks [256,1280): adj -> CSR compression (warp/row, prefetched stream)
// ---------------------------------------------------------------------------
__global__ __launch_bounds__(256) void k_fused1(
    const float* __restrict__ X, const float* __restrict__ B,
    const float* __restrict__ bias, __half* __restrict__ out,
    const float* __restrict__ adj) {
    const int tid = threadIdx.x;
    const int lane = tid & 31;
    const int wid = tid >> 5;

    if (blockIdx.x >= 256) {
        // ------- adj -> CSR compression (double-buffered stream) -------
        int row = (blockIdx.x - 256) * 8 + wid;
        const float4* a4 = (const float4*)(adj + (size_t)row * NN);
        const unsigned lt = (1u << lane) - 1u;
        uint2* pr = g_pairs + (size_t)row * CAP;
        int cnt = 0;
        float4 cur[4];
#pragma unroll
        for (int j = 0; j < 4; j++) cur[j] = __ldcs(&a4[j * 32 + lane]);
#pragma unroll 1
        for (int it = 0; it < 64; it += 4) {
            float4 nxt[4];
            if (it + 4 < 64) {
#pragma unroll
                for (int j = 0; j < 4; j++) nxt[j] = __ldcs(&a4[(it + 4 + j) * 32 + lane]);
            } else {
#pragma unroll
                for (int j = 0; j < 4; j++) nxt[j] = make_float4(0.f, 0.f, 0.f, 0.f);
            }
#pragma unroll
            for (int j = 0; j < 4; j++) {
                float vv[4] = {cur[j].x, cur[j].y, cur[j].z, cur[j].w};
#pragma unroll
                for (int c = 0; c < 4; c++) {
                    float v = vv[c];
                    unsigned m = __ballot_sync(0xffffffffu, v != 0.f);
                    if (v != 0.f) {
                        int pos = cnt + __popc(m & lt);
                        if (pos < CAP)
                            pr[pos] = make_uint2(((it + j) * 32 + lane) * 4 + c,
                                                 __float_as_uint(v));
                    }
                    cnt += __popc(m);
                }
            }
#pragma unroll
            for (int j = 0; j < 4; j++) cur[j] = nxt[j];
        }
        if (lane == 0) g_cnt[row] = cnt < CAP ? cnt : CAP;
        return;
    }

    // ---------------- GEMM1 (tf32 mma, K-chunked B) ----------------
    extern __shared__ char smraw[];
    float*    Asf = (float*)smraw;                       // [32][PA]
    uint32_t* Asu = (uint32_t*)smraw;
    uint32_t* Bsu = (uint32_t*)(smraw + 32 * PA * 4);    // [32][PB]
    float*    Cs  = (float*)smraw;                       // [32][PA] (reuse)
    const int br = blockIdx.x * 32;

#pragma unroll
    for (int i = 0; i < 4; i++) {
        int idx4 = tid + i * 256;
        int r = idx4 >> 5, c4 = idx4 & 31;
        ((float4*)(Asf + r * PA))[c4] = ((const float4*)(X + (size_t)(br + r) * FD))[c4];
    }
    __syncthreads();

#pragma unroll
    for (int r = 0; r < 4; r++) {
        int row = wid * 4 + r;
        float4 v = ((float4*)(Asf + row * PA))[lane];
        float ss = wsum(v.x * v.x + v.y * v.y + v.z * v.z + v.w * v.w);
        float n = fmaxf(sqrtf(ss), HEPS);
        float s = atanhf(fminf(n, MAXT)) / n;
        ((uint4*)(Asu + row * PA))[lane] =
            make_uint4(f2tf(v.x * s), f2tf(v.y * s), f2tf(v.z * s), f2tf(v.w * s));
    }

    const int qr = lane >> 2, qc = lane & 3;
    const int wm = (wid >> 2) * 16;
    const int wn = (wid & 3) * 32;
    float acc[4][4];
#pragma unroll
    for (int nt = 0; nt < 4; nt++)
#pragma unroll
        for (int c = 0; c < 4; c++) acc[nt][c] = 0.f;

#pragma unroll
    for (int chunk = 0; chunk < 4; chunk++) {
#pragma unroll
        for (int i = 0; i < 4; i++) {
            int idx4 = tid + i * 256;
            int k = idx4 >> 5, c4 = idx4 & 31;
            float4 v = ((const float4*)(B + (size_t)(chunk * 32 + k) * FD))[c4];
            ((uint4*)(Bsu + k * PB))[c4] =
                make_uint4(f2tf(v.x), f2tf(v.y), f2tf(v.z), f2tf(v.w));
        }
        __syncthreads();   // also orders log0 writes (chunk 0) vs mma reads
#pragma unroll
        for (int ks = 0; ks < 4; ks++) {
            int k0 = ks * 8;
            int ka = chunk * 32 + k0;
            uint32_t a0 = Asu[(wm + qr) * PA + ka + qc];
            uint32_t a1 = Asu[(wm + 8 + qr) * PA + ka + qc];
            uint32_t a2 = Asu[(wm + qr) * PA + ka + 4 + qc];
            uint32_t a3 = Asu[(wm + 8 + qr) * PA + ka + 4 + qc];
#pragma unroll
            for (int nt = 0; nt < 4; nt++) {
                int nb = wn + nt * 8;
                uint32_t b0 = Bsu[(k0 + qc) * PB + nb + qr];
                uint32_t b1 = Bsu[(k0 + 4 + qc) * PB + nb + qr];
                mma_tf32(acc[nt], a0, a1, a2, a3, b0, b1);
            }
        }
        __syncthreads();
    }

#pragma unroll
    for (int nt = 0; nt < 4; nt++) {
        int col = wn + nt * 8 + 2 * qc;
        *(float2*)&Cs[(wm + qr) * PA + col]     = make_float2(acc[nt][0], acc[nt][1]);
        *(float2*)&Cs[(wm + 8 + qr) * PA + col] = make_float2(acc[nt][2], acc[nt][3]);
    }
    __syncthreads();

    mobius_smem<0>(Cs, bias, br, wid, lane, out);
}

// ---------------------------------------------------------------------------
// k2: CSR gather + fused epilogue: W = log0(concat(x, exp0(adj @ V)))
// ---------------------------------------------------------------------------
__global__ __launch_bounds__(256) void k_gather(
    const __half* __restrict__ V, const float* __restrict__ x,
    __half* __restrict__ W) {
    int row = (blockIdx.x * blockDim.x + threadIdx.x) >> 5;
    int lane = threadIdx.x & 31;
    if (row >= NN) return;
    const int cnt = g_cnt[row];
    const uint2* pr = g_pairs + (size_t)row * CAP;
    float ax = 0.f, ay = 0.f, az = 0.f, aw = 0.f;

    int i = 0;
    for (; i + 8 <= cnt; i += 8) {
        uint4 q[4];
#pragma unroll
        for (int j = 0; j < 4; j++) q[j] = *(const uint4*)(pr + i + 2 * j);
        int   col[8];
        float val[8];
#pragma unroll
        for (int j = 0; j < 4; j++) {
            col[2 * j]     = (int)q[j].x; val[2 * j]     = __uint_as_float(q[j].y);
            col[2 * j + 1] = (int)q[j].z; val[2 * j + 1] = __uint_as_float(q[j].w);
        }
#pragma unroll
        for (int j = 0; j < 8; j++) {
            uint2 raw = ((const uint2*)(V + (size_t)col[j] * FD))[lane];
            float2 v01 = __half22float2(*(const __half2*)&raw.x);
            float2 v23 = __half22float2(*(const __half2*)&raw.y);
            ax += val[j] * v01.x; ay += val[j] * v01.y;
            az += val[j] * v23.x; aw += val[j] * v23.y;
        }
    }
    for (; i < cnt; i++) {
        uint2 p = pr[i];
        float aj = __uint_as_float(p.y);
        uint2 raw = ((const uint2*)(V + (size_t)p.x * FD))[lane];
        float2 v01 = __half22float2(*(const __half2*)&raw.x);
        float2 v23 = __half22float2(*(const __half2*)&raw.y);
        ax += aj * v01.x; ay += aj * v01.y;
        az += aj * v23.x; aw += aj * v23.y;
    }

    float ssa = wsum(ax * ax + ay * ay + az * az + aw * aw);
    float na = fmaxf(sqrtf(ssa), HEPS);
    float sa = tanhf(na) / na;
    float4 xv = ((const float4*)(x + (size_t)row * FD))[lane];
    float ssx = wsum(xv.x * xv.x + xv.y * xv.y + xv.z * xv.z + xv.w * xv.w);
    float tot = ssx + sa * sa * ssa;
    float n = fmaxf(sqrtf(tot), HEPS);
    float s = atanhf(fminf(n, MAXT)) / n;
    __half* wr = W + (size_t)row * 2 * FD;
    {
        __half2 h0 = __floats2half2_rn(s * xv.x, s * xv.y);
        __half2 h1 = __floats2half2_rn(s * xv.z, s * xv.w);
        ((uint2*)wr)[lane] = make_uint2(*(uint32_t*)&h0, *(uint32_t*)&h1);
    }
    {
        float sb = s * sa;
        __half2 h0 = __floats2half2_rn(sb * ax, sb * ay);
        __half2 h1 = __floats2half2_rn(sb * az, sb * aw);
        ((uint2*)(wr + FD))[lane] = make_uint2(*(uint32_t*)&h0, *(uint32_t*)&h1);
    }
}

// ---------------------------------------------------------------------------
// GEMM2 (tf32 mma, BM=32, K-CHUNKED B): out = h_add(exp0(W @ layer), lb).
// B in 8 chunks of 32 rows -> smem ~51 KB -> 4 CTAs/SM.
// ---------------------------------------------------------------------------
__global__ __launch_bounds__(256) void k_gemm2(
    const __half* __restrict__ A, const float* __restrict__ B,
    const float* __restrict__ bias, float* __restrict__ out) {
    extern __shared__ char smraw[];
    uint32_t* Asu = (uint32_t*)smraw;                     // [32][PA2]
    uint32_t* Bsu = (uint32_t*)(smraw + 32 * PA2 * 4);    // [32][PB]
    float*    Cs  = (float*)smraw;                        // [32][PA] (reuse)
    const int tid = threadIdx.x;
    const int lane = tid & 31;
    const int wid = tid >> 5;
    const int br = blockIdx.x * 32;

#pragma unroll
    for (int i = 0; i < 4; i++) {
        int idx8 = tid + i * 256;
        int r = idx8 >> 5, c8 = idx8 & 31;
        uint4 raw = ((const uint4*)(A + (size_t)(br + r) * (2 * FD)))[c8];
        const __half2* hp = (const __half2*)&raw;
        uint32_t* dst = Asu + r * PA2 + c8 * 8;
#pragma unroll
        for (int j = 0; j < 4; j++) {
            float2 f = __half22float2(hp[j]);
            dst[2 * j]     = f2tf(f.x);
            dst[2 * j + 1] = f2tf(f.y);
        }
    }

    const int qr = lane >> 2, qc = lane & 3;
    const int wm = (wid >> 2) * 16;
    const int wn = (wid & 3) * 32;
    float acc[4][4];
#pragma unroll
    for (int nt = 0; nt < 4; nt++)
#pragma unroll
        for (int c = 0; c < 4; c++) acc[nt][c] = 0.f;

#pragma unroll
    for (int chunk = 0; chunk < 8; chunk++) {
#pragma unroll
        for (int i = 0; i < 4; i++) {
            int idx4 = tid + i * 256;
            int k = idx4 >> 5, c4 = idx4 & 31;
            float4 v = ((const float4*)(B + (size_t)(chunk * 32 + k) * FD))[c4];
            ((uint4*)(Bsu + k * PB))[c4] =
                make_uint4(f2tf(v.x), f2tf(v.y), f2tf(v.z), f2tf(v.w));
        }
        __syncthreads();   // chunk 0: also orders A-convert writes vs mma reads
#pragma unroll
        for (int ks = 0; ks < 4; ks++) {
            int k0 = ks * 8;
            int ka = chunk * 32 + k0;
            uint32_t a0 = Asu[(wm + qr) * PA2 + ka + qc];
            uint32_t a1 = Asu[(wm + 8 + qr) * PA2 + ka + qc];
            uint32_t a2 = Asu[(wm + qr) * PA2 + ka + 4 + qc];
            uint32_t a3 = Asu[(wm + 8 + qr) * PA2 + ka + 4 + qc];
#pragma unroll
            for (int nt = 0; nt < 4; nt++) {
                int nb = wn + nt * 8;
                uint32_t b0 = Bsu[(k0 + qc) * PB + nb + qr];
                uint32_t b1 = Bsu[(k0 + 4 + qc) * PB + nb + qr];
                mma_tf32(acc[nt], a0, a1, a2, a3, b0, b1);
            }
        }
        __syncthreads();
    }

#pragma unroll
    for (int nt = 0; nt < 4; nt++) {
        int col = wn + nt * 8 + 2 * qc;
        *(float2*)&Cs[(wm + qr) * PA + col]     = make_float2(acc[nt][0], acc[nt][1]);
        *(float2*)&Cs[(wm + 8 + qr) * PA + col] = make_float2(acc[nt][2], acc[nt][3]);
    }
    __syncthreads();

    mobius_smem<1>(Cs, bias, br, wid, lane, out);
}

// ---------------------------------------------------------------------------
extern "C" void kernel_launch(void* const* d_in, const int* in_sizes, int n_in,
                              void* d_out, int out_size) {
    const float* x     = (const float*)d_in[0];
    const float* adj   = (const float*)d_in[1];
    const float* embed = (const float*)d_in[2];
    const float* layer = (const float*)d_in[3];
    const float* eb    = (const float*)d_in[4];
    const float* lb    = (const float*)d_in[5];
    float* out = (float*)d_out;
    (void)in_sizes; (void)n_in; (void)out_size;

    __half *pV, *pW;
    cudaGetSymbolAddress((void**)&pV, g_Vh);
    cudaGetSymbolAddress((void**)&pW, g_Wh);

    const int smem1 = (32 * PA + 32 * PB) * 4;    // ~34.3 KB
    const int smem2 = (32 * PA2 + 32 * PB) * 4;   // ~50.7 KB
    cudaFuncSetAttribute(k_fused1, cudaFuncAttributeMaxDynamicSharedMemorySize, smem1);
    cudaFuncSetAttribute(k_gemm2,  cudaFuncAttributeMaxDynamicSharedMemorySize, smem2);

    // 1. [gemm1: V = log0(h_add(exp0(log0(x)@embed),eb))] ∥ [adj -> CSR]
    k_fused1<<<256 + NN / 8, 256, smem1>>>(x, embed, eb, pV, adj);
    // 2. W = log0(concat(x, exp0(adj @ V)))  via CSR gather
    k_gather<<<NN / 8, 256>>>(pV, x, pW);
    // 3. out = h_add(exp0(W @ layer), lb)
    k_gemm2<<<NN / 32, 256, smem2>>>(pW, layer, lb, out);
}